// round 4
// baseline (speedup 1.0000x reference)
#include <cuda_runtime.h>
#include <math.h>

#define NBATCH 4
#define NHID   128
#define NCOL   65536
#define NMODE  256
#define NHS    8          // h-split for kmodes

// Scratch (allocation-free rule: device globals)
__device__ __align__(16) float g_yp[NHS * 2 * NBATCH * NHID * NMODE]; // 32 MB partials
__device__ __align__(16) float g_z[(size_t)NHID * NCOL];              // 33.5 MB: z[k][n]
//   n <  256 : raw  c[k,n] + lin_b[k]
//   n >= 256 : gelu(c[k,n] + lin_b[k])

__device__ __forceinline__ float gelu_exact(float v) {
    return 0.5f * v * (1.0f + erff(v * 0.70710678118654752440f));
}

// ---- packed f32x2 helpers (SASS FFMA2; PTX-only path on sm_103a) ----------
__device__ __forceinline__ unsigned long long pack2_dup(float v) {
    unsigned long long r;
    unsigned int u = __float_as_uint(v);
    asm("mov.b64 %0, {%1, %1};" : "=l"(r) : "r"(u));
    return r;
}
__device__ __forceinline__ void fma2(unsigned long long& d,
                                     unsigned long long a, unsigned long long b) {
    asm("fma.rn.f32x2 %0, %1, %2, %0;" : "+l"(d) : "l"(a), "l"(b));
}
__device__ __forceinline__ float2 unpack2(unsigned long long v) {
    unsigned int lo, hi;
    asm("mov.b64 {%0, %1}, %2;" : "=r"(lo), "=r"(hi) : "l"(v));
    return make_float2(__uint_as_float(lo), __uint_as_float(hi));
}

// ---------------------------------------------------------------------------
// Kernel A: per-mode GEMM, h split 8 ways (16 h per chunk).
//  g_yp[hs][ri][b][k][m] = sum_{h in chunk} x[b,h,m] * w_{ri}[h,k,m]
// grid (64 = 8 kb * 8 hs, 8 mb, 2 ri) = 1024 CTAs, 128 threads.
// Mainloop: explicit 8-deep w prefetch into registers (MLP=8).
// ---------------------------------------------------------------------------
__global__ void __launch_bounds__(128) kmodes(const float* __restrict__ x,
                                              const float* __restrict__ wr,
                                              const float* __restrict__ wi) {
    __shared__ float xs[NBATCH * 16 * 32];    // 8 KB
    const int kb = blockIdx.x >> 3, hs = blockIdx.x & 7;
    const int mb = blockIdx.y, ri = blockIdx.z;
    const float* w = ri ? wi : wr;
    const int m0 = mb * 32, k0 = kb * 16, h0 = hs * 16;
    const int tid = threadIdx.x;

    for (int i = tid; i < NBATCH * 16 * 8; i += 128) {
        int j = i & 7;
        int bh = i >> 3;
        int b = bh >> 4, h = bh & 15;
        float4 v = *reinterpret_cast<const float4*>(
            x + (size_t)(b * NHID + h0 + h) * NCOL + m0 + j * 4);
        *reinterpret_cast<float4*>(xs + bh * 32 + j * 4) = v;
    }
    __syncthreads();

    const int kl = tid & 15;
    const int mg = tid >> 4;
    const int k  = k0 + kl;
    const int mm = mg * 4;

    float a[NBATCH][4];
#pragma unroll
    for (int b = 0; b < NBATCH; b++)
#pragma unroll
        for (int j = 0; j < 4; j++) a[b][j] = 0.f;

    const float* wp = w + (size_t)h0 * NHID * NMODE + (size_t)k * NMODE + m0 + mm;
#pragma unroll
    for (int hh = 0; hh < 16; hh += 8) {
        float4 wv[8];
#pragma unroll
        for (int j = 0; j < 8; j++)
            wv[j] = __ldg(reinterpret_cast<const float4*>(
                wp + (size_t)(hh + j) * NHID * NMODE));
#pragma unroll
        for (int j = 0; j < 8; j++) {
#pragma unroll
            for (int b = 0; b < NBATCH; b++) {
                float4 xv = *reinterpret_cast<const float4*>(xs + (b * 16 + hh + j) * 32 + mm);
                a[b][0] += xv.x * wv[j].x;
                a[b][1] += xv.y * wv[j].y;
                a[b][2] += xv.z * wv[j].z;
                a[b][3] += xv.w * wv[j].w;
            }
        }
    }
#pragma unroll
    for (int b = 0; b < NBATCH; b++) {
        float4 v = make_float4(a[b][0], a[b][1], a[b][2], a[b][3]);
        *reinterpret_cast<float4*>(
            &g_yp[(((hs * 2 + ri) * NBATCH + b) * NHID + k) * NMODE + m0 + mm]) = v;
    }
}

// ---------------------------------------------------------------------------
// Kernel B: c[k,n] = sum_h lin_w[k,h]*bias[h,n] via FFMA2 -> g_z only.
//   n >= 256: g_z = gelu(c + lin_b[k]);   n < 256: g_z = c + lin_b[k] (raw)
// 1024 CTAs x 64 n-cols, 256 threads (16 kt x 16 nt), 8k x 4n per thread.
// ---------------------------------------------------------------------------
#define WPITCH 132
__global__ void __launch_bounds__(256, 2) kgemm(const float* __restrict__ bias,
                                                const float* __restrict__ lin_w,
                                                const float* __restrict__ lin_b) {
    extern __shared__ float sm[];
    float* wT = sm;                      // [h][k] pitch 132
    float* sb = sm + NHID * WPITCH;      // [h][64]
    __shared__ float slb[NHID];

    const int tid = threadIdx.x;
    const int n_base = blockIdx.x * 64;

    for (int i = tid; i < NHID * NHID; i += 256) {
        int h = i & 127, k = i >> 7;
        wT[h * WPITCH + k] = lin_w[i];
    }
    if (tid < NHID) slb[tid] = lin_b[tid];
    for (int i = tid; i < NHID * 16; i += 256) {
        int h = i >> 4, j = i & 15;
        float4 v = *reinterpret_cast<const float4*>(bias + (size_t)h * NCOL + n_base + j * 4);
        *reinterpret_cast<float4*>(sb + h * 64 + j * 4) = v;
    }
    __syncthreads();

    const int kt = tid >> 4;
    const int nt = tid & 15;

    unsigned long long acc2[4][4];   // [k-pair][n]
#pragma unroll
    for (int p = 0; p < 4; p++)
#pragma unroll
        for (int j = 0; j < 4; j++) acc2[p][j] = 0ULL;

    const float* wrow = wT + kt * 8;
    const float* bp = sb + nt * 4;
#pragma unroll 4
    for (int h = 0; h < NHID; h++) {
        float4 bv = *reinterpret_cast<const float4*>(bp + h * 64);
        ulonglong2 wA = *reinterpret_cast<const ulonglong2*>(wrow + h * WPITCH);
        ulonglong2 wB = *reinterpret_cast<const ulonglong2*>(wrow + h * WPITCH + 4);
        unsigned long long bn0 = pack2_dup(bv.x);
        unsigned long long bn1 = pack2_dup(bv.y);
        unsigned long long bn2 = pack2_dup(bv.z);
        unsigned long long bn3 = pack2_dup(bv.w);
        fma2(acc2[0][0], wA.x, bn0); fma2(acc2[0][1], wA.x, bn1);
        fma2(acc2[0][2], wA.x, bn2); fma2(acc2[0][3], wA.x, bn3);
        fma2(acc2[1][0], wA.y, bn0); fma2(acc2[1][1], wA.y, bn1);
        fma2(acc2[1][2], wA.y, bn2); fma2(acc2[1][3], wA.y, bn3);
        fma2(acc2[2][0], wB.x, bn0); fma2(acc2[2][1], wB.x, bn1);
        fma2(acc2[2][2], wB.x, bn2); fma2(acc2[2][3], wB.x, bn3);
        fma2(acc2[3][0], wB.y, bn0); fma2(acc2[3][1], wB.y, bn1);
        fma2(acc2[3][2], wB.y, bn2); fma2(acc2[3][3], wB.y, bn3);
    }

    const int n0 = n_base + nt * 4;
    const bool far = (n_base >= NMODE);
#pragma unroll
    for (int p = 0; p < 4; p++) {
        int k0 = kt * 8 + 2 * p;
        float lb0 = slb[k0], lb1 = slb[k0 + 1];
        float2 a0 = unpack2(acc2[p][0]);
        float2 a1 = unpack2(acc2[p][1]);
        float2 a2 = unpack2(acc2[p][2]);
        float2 a3 = unpack2(acc2[p][3]);
        float4 r0 = make_float4(a0.x + lb0, a1.x + lb0, a2.x + lb0, a3.x + lb0);
        float4 r1 = make_float4(a0.y + lb1, a1.y + lb1, a2.y + lb1, a3.y + lb1);
        if (far) {
            r0 = make_float4(gelu_exact(r0.x), gelu_exact(r0.y), gelu_exact(r0.z), gelu_exact(r0.w));
            r1 = make_float4(gelu_exact(r1.x), gelu_exact(r1.y), gelu_exact(r1.z), gelu_exact(r1.w));
        }
        *reinterpret_cast<float4*>(&g_z[(size_t)k0 * NCOL + n0]) = r0;
        *reinterpret_cast<float4*>(&g_z[(size_t)(k0 + 1) * NCOL + n0]) = r1;
    }
}

// ---------------------------------------------------------------------------
// Kernel W: streaming expander for n >= 256.
//   out[b,k,n,0] = g_z[k,n]; out[b,k,n,1] = 0   for all 4 b.
// grid (64, 128), 256 threads. One float4 of z -> 8 STG.128 per thread.
// ---------------------------------------------------------------------------
__global__ void __launch_bounds__(256) kwrite(float* __restrict__ out) {
    const int k = blockIdx.y;
    const int idx = blockIdx.x * 256 + threadIdx.x;   // float4 index past n=256
    if (idx >= (NCOL - NMODE) / 4) return;
    const int n0 = NMODE + idx * 4;
    float4 z = __ldg(reinterpret_cast<const float4*>(&g_z[(size_t)k * NCOL + n0]));
    float4 lo = make_float4(z.x, 0.f, z.y, 0.f);
    float4 hi = make_float4(z.z, 0.f, z.w, 0.f);
#pragma unroll
    for (int b = 0; b < NBATCH; b++) {
        float* op = out + 2 * ((size_t)(b * NHID + k) * NCOL + n0);
        __stcs(reinterpret_cast<float4*>(op),     lo);
        __stcs(reinterpret_cast<float4*>(op + 4), hi);
    }
}

// ---------------------------------------------------------------------------
// Kernel C: n < 256 region. Sums 8 h-partials of g_yp during staging.
//   out[b,k,n,0] = gelu(sum_h lin_w[k,h]*y_r + g_z[k,n]); out[...,1] = gelu(..y_i)
// grid 128 = (8 m-tiles of 32) x (4 b) x (4 k-blocks of 32), 256 threads
// ---------------------------------------------------------------------------
__global__ void __launch_bounds__(256) ksmall(const float* __restrict__ lin_w,
                                              float* __restrict__ out) {
    extern __shared__ float smc[];
    float* sW = smc;               // [32][129]
    float* sy = smc + 32 * 129;    // [ri*128+h][32]
    const int bx = blockIdx.x;
    const int mt = bx & 7, b = (bx >> 3) & 3, kb = bx >> 5;
    const int tid = threadIdx.x;
    const int m0 = mt * 32;

    for (int i = tid; i < 32 * NHID; i += 256) {
        int h = i & 127, r = i >> 7;
        sW[r * 129 + h] = lin_w[(kb * 32 + r) * NHID + h];
    }
    for (int i = tid; i < 2 * NHID * 8; i += 256) {
        int j = i & 7;
        int rh = i >> 3;
        int ri = rh >> 7, h = rh & 127;
        float4 s = make_float4(0.f, 0.f, 0.f, 0.f);
#pragma unroll
        for (int hsp = 0; hsp < NHS; hsp++) {
            float4 v = *reinterpret_cast<const float4*>(
                &g_yp[(((hsp * 2 + ri) * NBATCH + b) * NHID + h) * NMODE + m0 + j * 4]);
            s.x += v.x; s.y += v.y; s.z += v.z; s.w += v.w;
        }
        *reinterpret_cast<float4*>(sy + rh * 32 + j * 4) = s;
    }
    __syncthreads();

    const int kl = tid >> 3;
    const int ng = tid & 7;
    const int k = kb * 32 + kl;

    float ar[4] = {0.f, 0.f, 0.f, 0.f};
    float ai[4] = {0.f, 0.f, 0.f, 0.f};
    const float* wp  = sW + kl * 129;
    const float* yrp = sy + ng * 4;
    const float* yip = sy + NHID * 32 + ng * 4;
#pragma unroll 4
    for (int h = 0; h < NHID; h++) {
        float w = wp[h];
        float4 r4 = *reinterpret_cast<const float4*>(yrp + h * 32);
        float4 i4 = *reinterpret_cast<const float4*>(yip + h * 32);
        ar[0] += w * r4.x; ar[1] += w * r4.y; ar[2] += w * r4.z; ar[3] += w * r4.w;
        ai[0] += w * i4.x; ai[1] += w * i4.y; ai[2] += w * i4.z; ai[3] += w * i4.w;
    }
    const int n0 = m0 + ng * 4;
    float4 cv = *reinterpret_cast<const float4*>(&g_z[(size_t)k * NCOL + n0]);
    float4 lo = make_float4(gelu_exact(ar[0] + cv.x), gelu_exact(ai[0]),
                            gelu_exact(ar[1] + cv.y), gelu_exact(ai[1]));
    float4 hi = make_float4(gelu_exact(ar[2] + cv.z), gelu_exact(ai[2]),
                            gelu_exact(ar[3] + cv.w), gelu_exact(ai[3]));
    float* op = out + 2 * ((size_t)(b * NHID + k) * NCOL + n0);
    *reinterpret_cast<float4*>(op)     = lo;
    *reinterpret_cast<float4*>(op + 4) = hi;
}

// ---------------------------------------------------------------------------
extern "C" void kernel_launch(void* const* d_in, const int* in_sizes, int n_in,
                              void* d_out, int out_size) {
    const float* x     = (const float*)d_in[0];
    const float* wr    = (const float*)d_in[1];
    const float* wi    = (const float*)d_in[2];
    const float* bias  = (const float*)d_in[3];
    const float* lin_w = (const float*)d_in[4];
    const float* lin_b = (const float*)d_in[5];
    float* out = (float*)d_out;

    (void)in_sizes; (void)n_in; (void)out_size;

    const int kgemm_smem = (NHID * WPITCH + NHID * 64) * 4;   // 100352 B
    cudaFuncSetAttribute(kgemm,  cudaFuncAttributeMaxDynamicSharedMemorySize, kgemm_smem);
    cudaFuncSetAttribute(ksmall, cudaFuncAttributeMaxDynamicSharedMemorySize, 49280);

    kmodes<<<dim3(64, 8, 2), 128>>>(x, wr, wi);
    kgemm<<<1024, 256, kgemm_smem>>>(bias, lin_w, lin_b);
    kwrite<<<dim3(64, 128), 256>>>(out);
    ksmall<<<128, 256, 49280>>>(lin_w, out);
}

// round 5
// speedup vs baseline: 1.0036x; 1.0036x over previous
#include <cuda_runtime.h>
#include <math.h>

#define NBATCH 4
#define NHID   128
#define NCOL   65536
#define NMODE  256
#define NHS    8          // h-split for kmodes

// Scratch (allocation-free rule: device globals)
__device__ __align__(16) float g_yp[NHS * 2 * NBATCH * NHID * NMODE]; // 32 MB partials
__device__ __align__(16) float g_z[(size_t)NHID * NCOL];              // 33.5 MB: z[k][n]
//   n <  256 : raw  c[k,n] + lin_b[k]
//   n >= 256 : gelu(c[k,n] + lin_b[k])

__device__ __forceinline__ float gelu_exact(float v) {
    return 0.5f * v * (1.0f + erff(v * 0.70710678118654752440f));
}

// ---- packed f32x2 helpers (SASS FFMA2; PTX-only path on sm_103a) ----------
__device__ __forceinline__ unsigned long long pack2_dup(float v) {
    unsigned long long r;
    unsigned int u = __float_as_uint(v);
    asm("mov.b64 %0, {%1, %1};" : "=l"(r) : "r"(u));
    return r;
}
__device__ __forceinline__ void fma2(unsigned long long& d,
                                     unsigned long long a, unsigned long long b) {
    asm("fma.rn.f32x2 %0, %1, %2, %0;" : "+l"(d) : "l"(a), "l"(b));
}
__device__ __forceinline__ float2 unpack2(unsigned long long v) {
    unsigned int lo, hi;
    asm("mov.b64 {%0, %1}, %2;" : "=r"(lo), "=r"(hi) : "l"(v));
    return make_float2(__uint_as_float(lo), __uint_as_float(hi));
}

// ---------------------------------------------------------------------------
// Kernel A: per-mode GEMM, h split 8 ways (16 h per chunk).
//  g_yp[hs][ri][b][k][m] = sum_{h in chunk} x[b,h,m] * w_{ri}[h,k,m]
// grid (64 = 8 kb * 8 hs, 8 mb, 2 ri) = 1024 CTAs, 128 threads.
// Mainloop: explicit 8-deep w prefetch into registers (MLP=8).
// ---------------------------------------------------------------------------
__global__ void __launch_bounds__(128) kmodes(const float* __restrict__ x,
                                              const float* __restrict__ wr,
                                              const float* __restrict__ wi) {
    __shared__ float xs[NBATCH * 16 * 32];    // 8 KB
    const int kb = blockIdx.x >> 3, hs = blockIdx.x & 7;
    const int mb = blockIdx.y, ri = blockIdx.z;
    const float* w = ri ? wi : wr;
    const int m0 = mb * 32, k0 = kb * 16, h0 = hs * 16;
    const int tid = threadIdx.x;

    for (int i = tid; i < NBATCH * 16 * 8; i += 128) {
        int j = i & 7;
        int bh = i >> 3;
        int b = bh >> 4, h = bh & 15;
        float4 v = *reinterpret_cast<const float4*>(
            x + (size_t)(b * NHID + h0 + h) * NCOL + m0 + j * 4);
        *reinterpret_cast<float4*>(xs + bh * 32 + j * 4) = v;
    }
    __syncthreads();

    const int kl = tid & 15;
    const int mg = tid >> 4;
    const int k  = k0 + kl;
    const int mm = mg * 4;

    float a[NBATCH][4];
#pragma unroll
    for (int b = 0; b < NBATCH; b++)
#pragma unroll
        for (int j = 0; j < 4; j++) a[b][j] = 0.f;

    const float* wp = w + (size_t)h0 * NHID * NMODE + (size_t)k * NMODE + m0 + mm;
#pragma unroll
    for (int hh = 0; hh < 16; hh += 8) {
        float4 wv[8];
#pragma unroll
        for (int j = 0; j < 8; j++)
            wv[j] = __ldg(reinterpret_cast<const float4*>(
                wp + (size_t)(hh + j) * NHID * NMODE));
#pragma unroll
        for (int j = 0; j < 8; j++) {
#pragma unroll
            for (int b = 0; b < NBATCH; b++) {
                float4 xv = *reinterpret_cast<const float4*>(xs + (b * 16 + hh + j) * 32 + mm);
                a[b][0] += xv.x * wv[j].x;
                a[b][1] += xv.y * wv[j].y;
                a[b][2] += xv.z * wv[j].z;
                a[b][3] += xv.w * wv[j].w;
            }
        }
    }
#pragma unroll
    for (int b = 0; b < NBATCH; b++) {
        float4 v = make_float4(a[b][0], a[b][1], a[b][2], a[b][3]);
        *reinterpret_cast<float4*>(
            &g_yp[(((hs * 2 + ri) * NBATCH + b) * NHID + k) * NMODE + m0 + mm]) = v;
    }
}

// ---------------------------------------------------------------------------
// Kernel B: c[k,n] = sum_h lin_w[k,h]*bias[h,n] via FFMA2 -> g_z only.
//   n >= 256: g_z = gelu(c + lin_b[k]);   n < 256: g_z = c + lin_b[k] (raw)
// 1024 CTAs x 64 n-cols, 256 threads (16 kt x 16 nt), 8k x 4n per thread.
// ---------------------------------------------------------------------------
#define WPITCH 132
__global__ void __launch_bounds__(256, 2) kgemm(const float* __restrict__ bias,
                                                const float* __restrict__ lin_w,
                                                const float* __restrict__ lin_b) {
    extern __shared__ float sm[];
    float* wT = sm;                      // [h][k] pitch 132
    float* sb = sm + NHID * WPITCH;      // [h][64]
    __shared__ float slb[NHID];

    const int tid = threadIdx.x;
    const int n_base = blockIdx.x * 64;

    for (int i = tid; i < NHID * NHID; i += 256) {
        int h = i & 127, k = i >> 7;
        wT[h * WPITCH + k] = lin_w[i];
    }
    if (tid < NHID) slb[tid] = lin_b[tid];
    for (int i = tid; i < NHID * 16; i += 256) {
        int h = i >> 4, j = i & 15;
        float4 v = *reinterpret_cast<const float4*>(bias + (size_t)h * NCOL + n_base + j * 4);
        *reinterpret_cast<float4*>(sb + h * 64 + j * 4) = v;
    }
    __syncthreads();

    const int kt = tid >> 4;
    const int nt = tid & 15;

    unsigned long long acc2[4][4];   // [k-pair][n]
#pragma unroll
    for (int p = 0; p < 4; p++)
#pragma unroll
        for (int j = 0; j < 4; j++) acc2[p][j] = 0ULL;

    const float* wrow = wT + kt * 8;
    const float* bp = sb + nt * 4;
#pragma unroll 4
    for (int h = 0; h < NHID; h++) {
        float4 bv = *reinterpret_cast<const float4*>(bp + h * 64);
        ulonglong2 wA = *reinterpret_cast<const ulonglong2*>(wrow + h * WPITCH);
        ulonglong2 wB = *reinterpret_cast<const ulonglong2*>(wrow + h * WPITCH + 4);
        unsigned long long bn0 = pack2_dup(bv.x);
        unsigned long long bn1 = pack2_dup(bv.y);
        unsigned long long bn2 = pack2_dup(bv.z);
        unsigned long long bn3 = pack2_dup(bv.w);
        fma2(acc2[0][0], wA.x, bn0); fma2(acc2[0][1], wA.x, bn1);
        fma2(acc2[0][2], wA.x, bn2); fma2(acc2[0][3], wA.x, bn3);
        fma2(acc2[1][0], wA.y, bn0); fma2(acc2[1][1], wA.y, bn1);
        fma2(acc2[1][2], wA.y, bn2); fma2(acc2[1][3], wA.y, bn3);
        fma2(acc2[2][0], wB.x, bn0); fma2(acc2[2][1], wB.x, bn1);
        fma2(acc2[2][2], wB.x, bn2); fma2(acc2[2][3], wB.x, bn3);
        fma2(acc2[3][0], wB.y, bn0); fma2(acc2[3][1], wB.y, bn1);
        fma2(acc2[3][2], wB.y, bn2); fma2(acc2[3][3], wB.y, bn3);
    }

    const int n0 = n_base + nt * 4;
    const bool far = (n_base >= NMODE);
#pragma unroll
    for (int p = 0; p < 4; p++) {
        int k0 = kt * 8 + 2 * p;
        float lb0 = slb[k0], lb1 = slb[k0 + 1];
        float2 a0 = unpack2(acc2[p][0]);
        float2 a1 = unpack2(acc2[p][1]);
        float2 a2 = unpack2(acc2[p][2]);
        float2 a3 = unpack2(acc2[p][3]);
        float4 r0 = make_float4(a0.x + lb0, a1.x + lb0, a2.x + lb0, a3.x + lb0);
        float4 r1 = make_float4(a0.y + lb1, a1.y + lb1, a2.y + lb1, a3.y + lb1);
        if (far) {
            r0 = make_float4(gelu_exact(r0.x), gelu_exact(r0.y), gelu_exact(r0.z), gelu_exact(r0.w));
            r1 = make_float4(gelu_exact(r1.x), gelu_exact(r1.y), gelu_exact(r1.z), gelu_exact(r1.w));
        }
        *reinterpret_cast<float4*>(&g_z[(size_t)k0 * NCOL + n0]) = r0;
        *reinterpret_cast<float4*>(&g_z[(size_t)(k0 + 1) * NCOL + n0]) = r1;
    }
}

// ---------------------------------------------------------------------------
// Kernel W: streaming expander for n >= 256.
//   out[b,k,n,0] = g_z[k,n]; out[b,k,n,1] = 0   for all 4 b.
// grid (64, 128), 256 threads. One float4 of z -> 8 STG.128 per thread.
// ---------------------------------------------------------------------------
__global__ void __launch_bounds__(256) kwrite(float* __restrict__ out) {
    const int k = blockIdx.y;
    const int idx = blockIdx.x * 256 + threadIdx.x;   // float4 index past n=256
    if (idx >= (NCOL - NMODE) / 4) return;
    const int n0 = NMODE + idx * 4;
    float4 z = __ldg(reinterpret_cast<const float4*>(&g_z[(size_t)k * NCOL + n0]));
    float4 lo = make_float4(z.x, 0.f, z.y, 0.f);
    float4 hi = make_float4(z.z, 0.f, z.w, 0.f);
#pragma unroll
    for (int b = 0; b < NBATCH; b++) {
        float* op = out + 2 * ((size_t)(b * NHID + k) * NCOL + n0);
        __stcs(reinterpret_cast<float4*>(op),     lo);
        __stcs(reinterpret_cast<float4*>(op + 4), hi);
    }
}

// ---------------------------------------------------------------------------
// Kernel C: n < 256 region. Sums 8 h-partials of g_yp during staging.
//   out[b,k,n,0] = gelu(sum_h lin_w[k,h]*y_r + g_z[k,n]); out[...,1] = gelu(..y_i)
// grid 128 = (8 m-tiles of 32) x (4 b) x (4 k-blocks of 32), 256 threads
// ---------------------------------------------------------------------------
__global__ void __launch_bounds__(256) ksmall(const float* __restrict__ lin_w,
                                              float* __restrict__ out) {
    extern __shared__ float smc[];
    float* sW = smc;               // [32][129]
    float* sy = smc + 32 * 129;    // [ri*128+h][32]
    const int bx = blockIdx.x;
    const int mt = bx & 7, b = (bx >> 3) & 3, kb = bx >> 5;
    const int tid = threadIdx.x;
    const int m0 = mt * 32;

    for (int i = tid; i < 32 * NHID; i += 256) {
        int h = i & 127, r = i >> 7;
        sW[r * 129 + h] = lin_w[(kb * 32 + r) * NHID + h];
    }
    for (int i = tid; i < 2 * NHID * 8; i += 256) {
        int j = i & 7;
        int rh = i >> 3;
        int ri = rh >> 7, h = rh & 127;
        float4 s = make_float4(0.f, 0.f, 0.f, 0.f);
#pragma unroll
        for (int hsp = 0; hsp < NHS; hsp++) {
            float4 v = *reinterpret_cast<const float4*>(
                &g_yp[(((hsp * 2 + ri) * NBATCH + b) * NHID + h) * NMODE + m0 + j * 4]);
            s.x += v.x; s.y += v.y; s.z += v.z; s.w += v.w;
        }
        *reinterpret_cast<float4*>(sy + rh * 32 + j * 4) = s;
    }
    __syncthreads();

    const int kl = tid >> 3;
    const int ng = tid & 7;
    const int k = kb * 32 + kl;

    float ar[4] = {0.f, 0.f, 0.f, 0.f};
    float ai[4] = {0.f, 0.f, 0.f, 0.f};
    const float* wp  = sW + kl * 129;
    const float* yrp = sy + ng * 4;
    const float* yip = sy + NHID * 32 + ng * 4;
#pragma unroll 4
    for (int h = 0; h < NHID; h++) {
        float w = wp[h];
        float4 r4 = *reinterpret_cast<const float4*>(yrp + h * 32);
        float4 i4 = *reinterpret_cast<const float4*>(yip + h * 32);
        ar[0] += w * r4.x; ar[1] += w * r4.y; ar[2] += w * r4.z; ar[3] += w * r4.w;
        ai[0] += w * i4.x; ai[1] += w * i4.y; ai[2] += w * i4.z; ai[3] += w * i4.w;
    }
    const int n0 = m0 + ng * 4;
    float4 cv = *reinterpret_cast<const float4*>(&g_z[(size_t)k * NCOL + n0]);
    float4 lo = make_float4(gelu_exact(ar[0] + cv.x), gelu_exact(ai[0]),
                            gelu_exact(ar[1] + cv.y), gelu_exact(ai[1]));
    float4 hi = make_float4(gelu_exact(ar[2] + cv.z), gelu_exact(ai[2]),
                            gelu_exact(ar[3] + cv.w), gelu_exact(ai[3]));
    float* op = out + 2 * ((size_t)(b * NHID + k) * NCOL + n0);
    *reinterpret_cast<float4*>(op)     = lo;
    *reinterpret_cast<float4*>(op + 4) = hi;
}

// ---------------------------------------------------------------------------
extern "C" void kernel_launch(void* const* d_in, const int* in_sizes, int n_in,
                              void* d_out, int out_size) {
    const float* x     = (const float*)d_in[0];
    const float* wr    = (const float*)d_in[1];
    const float* wi    = (const float*)d_in[2];
    const float* bias  = (const float*)d_in[3];
    const float* lin_w = (const float*)d_in[4];
    const float* lin_b = (const float*)d_in[5];
    float* out = (float*)d_out;

    (void)in_sizes; (void)n_in; (void)out_size;

    const int kgemm_smem = (NHID * WPITCH + NHID * 64) * 4;   // 100352 B
    cudaFuncSetAttribute(kgemm,  cudaFuncAttributeMaxDynamicSharedMemorySize, kgemm_smem);
    cudaFuncSetAttribute(ksmall, cudaFuncAttributeMaxDynamicSharedMemorySize, 49280);

    kmodes<<<dim3(64, 8, 2), 128>>>(x, wr, wi);
    kgemm<<<1024, 256, kgemm_smem>>>(bias, lin_w, lin_b);
    kwrite<<<dim3(64, 128), 256>>>(out);
    ksmall<<<128, 256, 49280>>>(lin_w, out);
}